// round 2
// baseline (speedup 1.0000x reference)
#include <cuda_runtime.h>

// SO3 sparse CG tensor product, LMAX=2 (S=9), N_FEAT=128, N_ATOMS=30000.
// out[a, io, f] += cg[p] * x1[a, i1[p], f] * x2[a, i2[p], f]
//
// Strategy:
//  1) setup_kernel (1 thread): stable counting-sort of the ~83 paths by idx_out
//     into __device__ globals (deterministic order -> deterministic FP sums).
//  2) tp_kernel: block = 4 atoms x 128 feats. Stage x1/x2 rows (9x128 each) in
//     shared via a contiguous float4 copy; each thread owns one (atom, float4).
//     io-loop unrolled (register accumulator), inner path loop reads broadcast
//     path tables from shared and does 2 conflict-free LDS.128 + packed f32x2
//     mul/fma. Output written as coalesced STG.128, full coverage (no pre-zero).

#define MAXP 768          // cg_sparse can be at most 9*9*9=729 entries
#define ATOMS_PER_BLOCK 4
#define NTHREADS 128
#define F4_PER_ATOM 288   // 9 s-indices * 32 float4 per row

__device__ int   g_starts[10];
__device__ int   g_pidx[MAXP];   // i1 | (i2 << 8)
__device__ float g_pcg[MAXP];

__global__ void so3_setup_kernel(const float* __restrict__ cg,
                                 const int* __restrict__ i1,
                                 const int* __restrict__ i2,
                                 const int* __restrict__ io,
                                 int P) {
    if (threadIdx.x != 0 || blockIdx.x != 0) return;
    if (P > MAXP) P = MAXP;
    int cnt[9];
#pragma unroll
    for (int k = 0; k < 9; ++k) cnt[k] = 0;
    for (int p = 0; p < P; ++p) {
        int o = io[p];
        if (o >= 0 && o < 9) cnt[o]++;
    }
    int st[10];
    st[0] = 0;
#pragma unroll
    for (int k = 0; k < 9; ++k) st[k + 1] = st[k] + cnt[k];
#pragma unroll
    for (int k = 0; k < 10; ++k) g_starts[k] = st[k];
    int cur[9];
#pragma unroll
    for (int k = 0; k < 9; ++k) cur[k] = st[k];
    for (int p = 0; p < P; ++p) {
        int o = io[p];
        if (o < 0 || o >= 9) continue;
        int d = cur[o]++;
        g_pidx[d] = (i1[p] & 0xff) | ((i2[p] & 0xff) << 8);
        g_pcg[d]  = cg[p];
    }
}

__global__ __launch_bounds__(NTHREADS)
void so3_tp_kernel(const float* __restrict__ x1,
                   const float* __restrict__ x2,
                   float* __restrict__ out,
                   int natoms) {
    __shared__ ulonglong2 s1[ATOMS_PER_BLOCK * F4_PER_ATOM];
    __shared__ ulonglong2 s2[ATOMS_PER_BLOCK * F4_PER_ATOM];
    __shared__ int   s_starts[10];
    __shared__ int   s_pidx[MAXP];
    __shared__ float s_pcg[MAXP];

    const int tid = threadIdx.x;
    const long long a0 = (long long)blockIdx.x * ATOMS_PER_BLOCK;
    const int atoms_here = (natoms - a0 < ATOMS_PER_BLOCK) ? (int)(natoms - a0)
                                                           : ATOMS_PER_BLOCK;

    // Path tables -> shared (uniform broadcast data).
    const int P = g_starts[9];
    for (int p = tid; p < P; p += NTHREADS) {
        s_pidx[p] = g_pidx[p];
        s_pcg[p]  = g_pcg[p];
    }
    if (tid < 10) s_starts[tid] = g_starts[tid];

    // Stage input rows: contiguous float4 copy of [atoms_here, 9, 128] floats.
    const ulonglong2* gx1 =
        reinterpret_cast<const ulonglong2*>(x1) + a0 * F4_PER_ATOM;
    const ulonglong2* gx2 =
        reinterpret_cast<const ulonglong2*>(x2) + a0 * F4_PER_ATOM;
    const int nv = atoms_here * F4_PER_ATOM;
    for (int i = tid; i < nv; i += NTHREADS) {
        s1[i] = gx1[i];
        s2[i] = gx2[i];
    }
    __syncthreads();

    const int a  = tid >> 5;   // atom within block (one warp per atom)
    const int f4 = tid & 31;   // float4 index within the 128-feature row

    if (a < atoms_here) {
        const int base = a * F4_PER_ATOM + f4;
        ulonglong2* o4 = reinterpret_cast<ulonglong2*>(out) +
                         (a0 + a) * F4_PER_ATOM + f4;
#pragma unroll
        for (int io = 0; io < 9; ++io) {
            unsigned long long accx = 0ull;  // two packed +0.0f
            unsigned long long accy = 0ull;
            const int pend = s_starts[io + 1];
            for (int p = s_starts[io]; p < pend; ++p) {
                const int   ii = s_pidx[p];
                const float cg = s_pcg[p];
                unsigned long long cg2;
                asm("mov.b64 %0, {%1, %1};" : "=l"(cg2) : "f"(cg));
                const ulonglong2 v1 = s1[base + (ii & 0xff) * 32];
                const ulonglong2 v2 = s2[base + (ii >> 8) * 32];
                unsigned long long t0, t1;
                asm("mul.rn.f32x2 %0, %1, %2;" : "=l"(t0) : "l"(v1.x), "l"(v2.x));
                asm("mul.rn.f32x2 %0, %1, %2;" : "=l"(t1) : "l"(v1.y), "l"(v2.y));
                asm("fma.rn.f32x2 %0, %1, %2, %3;"
                    : "=l"(accx) : "l"(t0), "l"(cg2), "l"(accx));
                asm("fma.rn.f32x2 %0, %1, %2, %3;"
                    : "=l"(accy) : "l"(t1), "l"(cg2), "l"(accy));
            }
            ulonglong2 res;
            res.x = accx;
            res.y = accy;
            o4[io * 32] = res;
        }
    }
}

extern "C" void kernel_launch(void* const* d_in, const int* in_sizes, int n_in,
                              void* d_out, int out_size) {
    const float* x1 = (const float*)d_in[0];
    const float* x2 = (const float*)d_in[1];
    const float* cg = (const float*)d_in[2];
    const int*   i1 = (const int*)d_in[3];
    const int*   i2 = (const int*)d_in[4];
    const int*   io = (const int*)d_in[5];
    float* out = (float*)d_out;

    const int P      = in_sizes[2];
    const int natoms = in_sizes[0] / (9 * 128);

    so3_setup_kernel<<<1, 32>>>(cg, i1, i2, io, P);

    const int nblocks = (natoms + ATOMS_PER_BLOCK - 1) / ATOMS_PER_BLOCK;
    so3_tp_kernel<<<nblocks, NTHREADS>>>(x1, x2, out, natoms);
}

// round 3
// speedup vs baseline: 1.4165x; 1.4165x over previous
#include <cuda_runtime.h>

// SO3 sparse CG tensor product, LMAX=2 (S=9), N_FEAT=128.
//   out[a, io, f] = sum_p cg[p] * x1[a, i1[p], f] * x2[a, i2[p], f]
//
// The nonzero support of the real-basis CG tensor (83 triples for lmax=2) is
// hardcoded at compile time -> fully register-resident unrolled FMA chain, no
// shared memory, no inner-loop LDS. Values come from the runtime cg_sparse via
// an order-independent matching setup kernel. If the runtime structure doesn't
// match the hardcoded support, a generic fallback branch guarantees correctness.

// X(slot, i1, i2, io) — 83 triples, grouped by io for static accumulators.
#define PATHS(X) \
  X(0,0,0,0) X(1,1,1,0) X(2,2,2,0) X(3,3,3,0) X(4,4,4,0) X(5,5,5,0) X(6,6,6,0) X(7,7,7,0) X(8,8,8,0) \
  X(9,0,1,1) X(10,1,0,1) X(11,1,6,1) X(12,1,8,1) X(13,3,4,1) X(14,2,5,1) X(15,6,1,1) X(16,8,1,1) X(17,4,3,1) X(18,5,2,1) \
  X(19,0,2,2) X(20,2,0,2) X(21,1,5,2) X(22,2,6,2) X(23,3,7,2) X(24,5,1,2) X(25,6,2,2) X(26,7,3,2) \
  X(27,0,3,3) X(28,3,0,3) X(29,1,4,3) X(30,2,7,3) X(31,3,6,3) X(32,3,8,3) X(33,4,1,3) X(34,7,2,3) X(35,6,3,3) X(36,8,3,3) \
  X(37,0,4,4) X(38,4,0,4) X(39,1,3,4) X(40,3,1,4) X(41,4,6,4) X(42,5,7,4) X(43,6,4,4) X(44,7,5,4) \
  X(45,0,5,5) X(46,5,0,5) X(47,1,2,5) X(48,2,1,5) X(49,4,7,5) X(50,5,6,5) X(51,5,8,5) X(52,6,5,5) X(53,7,4,5) X(54,8,5,5) \
  X(55,0,6,6) X(56,6,0,6) X(57,1,1,6) X(58,2,2,6) X(59,3,3,6) X(60,4,4,6) X(61,5,5,6) X(62,6,6,6) X(63,7,7,6) X(64,8,8,6) \
  X(65,0,7,7) X(66,7,0,7) X(67,2,3,7) X(68,3,2,7) X(69,4,5,7) X(70,5,4,7) X(71,6,7,7) X(72,7,6,7) X(73,7,8,7) X(74,8,7,7) \
  X(75,0,8,8) X(76,8,0,8) X(77,1,1,8) X(78,3,3,8) X(79,5,5,8) X(80,6,8,8) X(81,7,7,8) X(82,8,6,8)

#define NSLOT 83

__device__ unsigned long long g_cgv2[NSLOT];  // (cg, cg) packed f32x2 per slot
__device__ int g_ok;

__global__ void so3_setup_kernel(const float* __restrict__ cg,
                                 const int* __restrict__ i1,
                                 const int* __restrict__ i2,
                                 const int* __restrict__ io,
                                 int P) {
    if (threadIdx.x != 0 || blockIdx.x != 0) return;
#define X(s, a, b, c) (((a) << 8) | ((b) << 4) | (c)),
    const int trip[NSLOT] = { PATHS(X) };
#undef X
    float vals[NSLOT];
    for (int t = 0; t < NSLOT; ++t) vals[t] = 0.0f;
    int ok = 1;
    for (int p = 0; p < P; ++p) {
        const int a = i1[p], b = i2[p], c = io[p];
        if (a < 0 || a > 8 || b < 0 || b > 8 || c < 0 || c > 8) { ok = 0; continue; }
        const int code = (a << 8) | (b << 4) | c;
        int found = 0;
        for (int t = 0; t < NSLOT; ++t) {
            if (trip[t] == code) { vals[t] += cg[p]; found = 1; break; }
        }
        if (!found) ok = 0;  // structure outside hardcoded support -> fallback
    }
    for (int t = 0; t < NSLOT; ++t) {
        const unsigned int u = __float_as_uint(vals[t]);
        g_cgv2[t] = ((unsigned long long)u << 32) | (unsigned long long)u;
    }
    g_ok = ok;
}

#define NTHREADS 256
#define ATOMS_PER_BLOCK 4   // 64 float2-threads per atom

__global__ __launch_bounds__(NTHREADS)
void so3_tp_kernel(const float* __restrict__ x1,
                   const float* __restrict__ x2,
                   float* __restrict__ out,
                   int natoms,
                   const float* __restrict__ cg,
                   const int* __restrict__ i1,
                   const int* __restrict__ i2,
                   const int* __restrict__ io,
                   int P) {
    const int tid  = threadIdx.x;
    const int a_in = tid >> 6;          // atom within block
    const int f2   = tid & 63;          // float2 index within 128-feature row
    const long long atom = (long long)blockIdx.x * ATOMS_PER_BLOCK + a_in;
    if (atom >= natoms) return;

    const long long base = atom * 1152 + (long long)f2 * 2;  // floats

    if (__ldg(&g_ok)) {
        // ---- fast path: fully register-resident ----
        unsigned long long x1r[9], x2r[9], acc[9];
#pragma unroll
        for (int s = 0; s < 9; ++s) {
            x1r[s] = __ldg(reinterpret_cast<const unsigned long long*>(x1 + base + s * 128));
            x2r[s] = __ldg(reinterpret_cast<const unsigned long long*>(x2 + base + s * 128));
            acc[s] = 0ull;  // two packed +0.0f
        }
        unsigned long long t;
#define X(s, a, b, c)                                                      \
        {                                                                  \
            const unsigned long long cg2 = __ldg(&g_cgv2[s]);              \
            asm("mul.rn.f32x2 %0, %1, %2;"                                 \
                : "=l"(t) : "l"(x1r[a]), "l"(x2r[b]));                     \
            asm("fma.rn.f32x2 %0, %1, %2, %3;"                             \
                : "=l"(acc[c]) : "l"(t), "l"(cg2), "l"(acc[c]));           \
        }
        PATHS(X)
#undef X
#pragma unroll
        for (int s = 0; s < 9; ++s) {
            *reinterpret_cast<unsigned long long*>(out + base + s * 128) = acc[s];
        }
    } else {
        // ---- generic fallback: always correct for any sparse structure ----
        float accx[9], accy[9];
#pragma unroll
        for (int s = 0; s < 9; ++s) { accx[s] = 0.0f; accy[s] = 0.0f; }
        for (int p = 0; p < P; ++p) {
            const int a = i1[p], b = i2[p], c = io[p];
            const float v = cg[p];
            const float2 u = *reinterpret_cast<const float2*>(x1 + base + a * 128);
            const float2 w = *reinterpret_cast<const float2*>(x2 + base + b * 128);
            accx[c] += v * u.x * w.x;
            accy[c] += v * u.y * w.y;
        }
#pragma unroll
        for (int s = 0; s < 9; ++s) {
            float2 r;
            r.x = accx[s];
            r.y = accy[s];
            *reinterpret_cast<float2*>(out + base + s * 128) = r;
        }
    }
}

extern "C" void kernel_launch(void* const* d_in, const int* in_sizes, int n_in,
                              void* d_out, int out_size) {
    const float* x1 = (const float*)d_in[0];
    const float* x2 = (const float*)d_in[1];
    const float* cg = (const float*)d_in[2];
    const int*   i1 = (const int*)d_in[3];
    const int*   i2 = (const int*)d_in[4];
    const int*   io = (const int*)d_in[5];
    float* out = (float*)d_out;

    const int P      = in_sizes[2];
    const int natoms = in_sizes[0] / (9 * 128);

    so3_setup_kernel<<<1, 32>>>(cg, i1, i2, io, P);

    const int nblocks = (natoms + ATOMS_PER_BLOCK - 1) / ATOMS_PER_BLOCK;
    so3_tp_kernel<<<nblocks, NTHREADS>>>(x1, x2, out, natoms, cg, i1, i2, io, P);
}

// round 4
// speedup vs baseline: 1.9203x; 1.3556x over previous
#include <cuda_runtime.h>

// SO3 sparse CG tensor product, LMAX=2 (S=9), N_FEAT=128.
//   out[a, io, f] = sum_p cg[p] * x1[a, i1[p], f] * x2[a, i2[p], f]
//
// Hardcoded 83-triple support (compile-time -> register-resident unrolled
// f32x2 FMA chain). Values matched from runtime cg_sparse by a PARALLEL setup
// kernel; mismatch -> generic fallback branch (always correct).
// tp kernel: thread = (atom, float4). 9 LDG.128 per input, 9 STG.128 out,
// cg staged in shared (uniform LDS.64 broadcasts, off the L1tex path).

// X(slot, i1, i2, io) — 83 triples, grouped by io.
#define PATHS(X) \
  X(0,0,0,0) X(1,1,1,0) X(2,2,2,0) X(3,3,3,0) X(4,4,4,0) X(5,5,5,0) X(6,6,6,0) X(7,7,7,0) X(8,8,8,0) \
  X(9,0,1,1) X(10,1,0,1) X(11,1,6,1) X(12,1,8,1) X(13,3,4,1) X(14,2,5,1) X(15,6,1,1) X(16,8,1,1) X(17,4,3,1) X(18,5,2,1) \
  X(19,0,2,2) X(20,2,0,2) X(21,1,5,2) X(22,2,6,2) X(23,3,7,2) X(24,5,1,2) X(25,6,2,2) X(26,7,3,2) \
  X(27,0,3,3) X(28,3,0,3) X(29,1,4,3) X(30,2,7,3) X(31,3,6,3) X(32,3,8,3) X(33,4,1,3) X(34,7,2,3) X(35,6,3,3) X(36,8,3,3) \
  X(37,0,4,4) X(38,4,0,4) X(39,1,3,4) X(40,3,1,4) X(41,4,6,4) X(42,5,7,4) X(43,6,4,4) X(44,7,5,4) \
  X(45,0,5,5) X(46,5,0,5) X(47,1,2,5) X(48,2,1,5) X(49,4,7,5) X(50,5,6,5) X(51,5,8,5) X(52,6,5,5) X(53,7,4,5) X(54,8,5,5) \
  X(55,0,6,6) X(56,6,0,6) X(57,1,1,6) X(58,2,2,6) X(59,3,3,6) X(60,4,4,6) X(61,5,5,6) X(62,6,6,6) X(63,7,7,6) X(64,8,8,6) \
  X(65,0,7,7) X(66,7,0,7) X(67,2,3,7) X(68,3,2,7) X(69,4,5,7) X(70,5,4,7) X(71,6,7,7) X(72,7,6,7) X(73,7,8,7) X(74,8,7,7) \
  X(75,0,8,8) X(76,8,0,8) X(77,1,1,8) X(78,3,3,8) X(79,5,5,8) X(80,6,8,8) X(81,7,7,8) X(82,8,6,8)

#define NSLOT 83
#define MAXP  768

__device__ unsigned long long g_cgv2[NSLOT];  // (cg, cg) packed per slot
__device__ int g_ok;

#define X(s, a, b, c) (((a) << 8) | ((b) << 4) | (c)),
__device__ const int g_trip[NSLOT] = { PATHS(X) };
#undef X

// Parallel setup: one block. Stage paths in shared, slot-parallel matching.
__global__ void so3_setup_kernel(const float* __restrict__ cg,
                                 const int* __restrict__ i1,
                                 const int* __restrict__ i2,
                                 const int* __restrict__ io,
                                 int P) {
    __shared__ int   s_code[MAXP];
    __shared__ float s_val[MAXP];
    __shared__ int   s_ok;

    const int tid = threadIdx.x;
    if (tid == 0) s_ok = (P <= MAXP) ? 1 : 0;
    const int Pc = (P <= MAXP) ? P : MAXP;
    __syncthreads();

    for (int p = tid; p < Pc; p += blockDim.x) {
        const int a = i1[p], b = i2[p], c = io[p];
        if (a < 0 || a > 8 || b < 0 || b > 8 || c < 0 || c > 8) {
            s_code[p] = -1;
            s_ok = 0;  // benign race: only ever writes 0
        } else {
            s_code[p] = (a << 8) | (b << 4) | c;
        }
        s_val[p] = cg[p];
    }
    __syncthreads();

    // One thread per hardcoded slot: sum all matching runtime entries.
    if (tid < NSLOT) {
        const int code = g_trip[tid];
        float v = 0.0f;
        for (int p = 0; p < Pc; ++p)
            if (s_code[p] == code) v += s_val[p];
        const unsigned int u = __float_as_uint(v);
        g_cgv2[tid] = ((unsigned long long)u << 32) | (unsigned long long)u;
    }

    // One thread per runtime path: membership check.
    for (int p = tid; p < Pc; p += blockDim.x) {
        const int code = s_code[p];
        int found = 0;
        for (int t = 0; t < NSLOT; ++t)
            if (g_trip[t] == code) { found = 1; break; }
        if (!found) s_ok = 0;
    }
    __syncthreads();
    if (tid == 0) g_ok = s_ok;
}

#define NTHREADS 128
#define ATOMS_PER_BLOCK 4   // one warp per atom, 32 float4-threads per row

__global__ __launch_bounds__(NTHREADS)
void so3_tp_kernel(const float* __restrict__ x1,
                   const float* __restrict__ x2,
                   float* __restrict__ out,
                   int natoms,
                   const float* __restrict__ cg,
                   const int* __restrict__ i1,
                   const int* __restrict__ i2,
                   const int* __restrict__ io,
                   int P) {
    __shared__ unsigned long long s_cg[NSLOT];
    __shared__ int s_ok;

    const int tid = threadIdx.x;
    if (tid < NSLOT) s_cg[tid] = g_cgv2[tid];
    if (tid == NSLOT) s_ok = g_ok;
    __syncthreads();

    const int a_in = tid >> 5;          // atom within block
    const int lane = tid & 31;          // float4 index within 128-feature row
    const long long atom = (long long)blockIdx.x * ATOMS_PER_BLOCK + a_in;
    if (atom >= natoms) return;

    const long long base = atom * 1152 + (long long)lane * 4;  // floats

    if (s_ok) {
        // ---- fast path: register-resident, packed f32x2 ----
        ulonglong2 x1r[9], x2r[9], acc[9];
#pragma unroll
        for (int s = 0; s < 9; ++s) {
            x1r[s] = __ldg(reinterpret_cast<const ulonglong2*>(x1 + base + s * 128));
            x2r[s] = __ldg(reinterpret_cast<const ulonglong2*>(x2 + base + s * 128));
            acc[s].x = 0ull;
            acc[s].y = 0ull;
        }
        unsigned long long t0, t1;
#define X(s, a, b, c)                                                       \
        {                                                                   \
            const unsigned long long cg2 = s_cg[s];                         \
            asm("mul.rn.f32x2 %0, %1, %2;"                                  \
                : "=l"(t0) : "l"(x1r[a].x), "l"(x2r[b].x));                 \
            asm("mul.rn.f32x2 %0, %1, %2;"                                  \
                : "=l"(t1) : "l"(x1r[a].y), "l"(x2r[b].y));                 \
            asm("fma.rn.f32x2 %0, %1, %2, %3;"                              \
                : "=l"(acc[c].x) : "l"(t0), "l"(cg2), "l"(acc[c].x));       \
            asm("fma.rn.f32x2 %0, %1, %2, %3;"                              \
                : "=l"(acc[c].y) : "l"(t1), "l"(cg2), "l"(acc[c].y));       \
        }
        PATHS(X)
#undef X
#pragma unroll
        for (int s = 0; s < 9; ++s) {
            *reinterpret_cast<ulonglong2*>(out + base + s * 128) = acc[s];
        }
    } else {
        // ---- generic fallback: always correct for any sparse structure ----
        float4 acc[9];
#pragma unroll
        for (int s = 0; s < 9; ++s) acc[s] = make_float4(0.f, 0.f, 0.f, 0.f);
        for (int p = 0; p < P; ++p) {
            const int a = i1[p], b = i2[p], c = io[p];
            const float v = cg[p];
            const float4 u = *reinterpret_cast<const float4*>(x1 + base + a * 128);
            const float4 w = *reinterpret_cast<const float4*>(x2 + base + b * 128);
            acc[c].x += v * u.x * w.x;
            acc[c].y += v * u.y * w.y;
            acc[c].z += v * u.z * w.z;
            acc[c].w += v * u.w * w.w;
        }
#pragma unroll
        for (int s = 0; s < 9; ++s)
            *reinterpret_cast<float4*>(out + base + s * 128) = acc[s];
    }
}

extern "C" void kernel_launch(void* const* d_in, const int* in_sizes, int n_in,
                              void* d_out, int out_size) {
    const float* x1 = (const float*)d_in[0];
    const float* x2 = (const float*)d_in[1];
    const float* cg = (const float*)d_in[2];
    const int*   i1 = (const int*)d_in[3];
    const int*   i2 = (const int*)d_in[4];
    const int*   io = (const int*)d_in[5];
    float* out = (float*)d_out;

    const int P      = in_sizes[2];
    const int natoms = in_sizes[0] / (9 * 128);

    so3_setup_kernel<<<1, 128>>>(cg, i1, i2, io, P);

    const int nblocks = (natoms + ATOMS_PER_BLOCK - 1) / ATOMS_PER_BLOCK;
    so3_tp_kernel<<<nblocks, NTHREADS>>>(x1, x2, out, natoms, cg, i1, i2, io, P);
}